// round 16
// baseline (speedup 1.0000x reference)
#include <cuda_runtime.h>
#include <cuda_bf16.h>
#include <cstdint>

// ---------------- static scratch (allocation-free rule) ----------------
#define V_MAX     262144
#define B_MAX     8
#define TILE      4096
#define TILES_MAX 64
#define SW        256          // positions per pipeline step
#define SEG_MAX   65536        // fast-path limit (u16 positions)

__device__ unsigned long long g_recA[V_MAX];
__device__ unsigned long long g_recB[V_MAX];
__device__ unsigned int       g_hist[B_MAX * TILES_MAX * 256];
__device__ int                g_order[V_MAX];
__device__ unsigned short     g_posMap[V_MAX];   // vertex -> in-segment position
__device__ int                g_selLocal[V_MAX];
__device__ int                g_ggLocal[V_MAX];
__device__ int                g_segCount[B_MAX];
__device__ int                g_rsn[B_MAX + 1];

// ---------------- sort: pack (+ init ggLocal to INT_MAX) ----------------
__global__ void packK(const float* __restrict__ hier, int V) {
    int i = blockIdx.x * blockDim.x + threadIdx.x;
    if (i >= V) return;
    unsigned bits = __float_as_uint(hier[i]);
    unsigned m = (unsigned)(-(int)(bits >> 31)) | 0x80000000u;   // order-preserving
    unsigned u = bits ^ m;
    g_recA[i] = ((unsigned long long)u << 32) | (unsigned)i;
    g_ggLocal[i] = 0x7FFFFFFF;
}

// ---------------- sort: per-(segment,tile) histogram ----------------
__global__ void histK(int dir, int shift, int TILES, const int* __restrict__ rs) {
    const unsigned long long* in = dir ? g_recB : g_recA;
    int seg = blockIdx.y;
    int s0 = rs[seg], s1 = rs[seg + 1];
    __shared__ unsigned int h[256];
    if (threadIdx.x < 256) h[threadIdx.x] = 0u;
    __syncthreads();
    int base = s0 + blockIdx.x * TILE;
    int n = min(TILE, s1 - base);
    for (int p = threadIdx.x; p < n; p += blockDim.x) {
        unsigned d = (unsigned)(in[base + p] >> shift) & 0xFFu;
        atomicAdd(&h[d], 1u);
    }
    __syncthreads();
    if (threadIdx.x < 256)
        g_hist[(seg * TILES + blockIdx.x) * 256 + threadIdx.x] = h[threadIdx.x];
}

// ---------------- sort: scan (per segment) ----------------
__global__ void scanK(int TILES, const int* __restrict__ rs) {
    int seg = blockIdx.x;
    int s0 = rs[seg];
    int d = threadIdx.x;            // 256 threads, one digit each
    unsigned run = 0;
    for (int t = 0; t < TILES; t++) {
        unsigned idx = (seg * TILES + t) * 256 + d;
        unsigned c = g_hist[idx];
        g_hist[idx] = run;
        run += c;
    }
    __shared__ unsigned tot[256];
    __shared__ unsigned start[256];
    tot[d] = run;
    __syncthreads();
    if (d == 0) {
        unsigned a = 0;
        for (int q = 0; q < 256; q++) { start[q] = a; a += tot[q]; }
    }
    __syncthreads();
    unsigned add = start[d] + (unsigned)s0;
    for (int t = 0; t < TILES; t++)
        g_hist[(seg * TILES + t) * 256 + d] += add;
}

// ---------------- sort: stable scatter (match_any warp ranking) ----------------
__global__ void scatterK(int dir, int shift, int TILES, const int* __restrict__ rs) {
    const unsigned long long* in  = dir ? g_recB : g_recA;
    unsigned long long*       out = dir ? g_recA : g_recB;
    int seg = blockIdx.y;
    int s0 = rs[seg], s1 = rs[seg + 1];
    int base = s0 + blockIdx.x * TILE;
    int n = min(TILE, s1 - base);
    if (n <= 0) return;

    __shared__ unsigned s_ofs[256];
    __shared__ unsigned s_cnt[8][256];
    int tid = threadIdx.x, lane = tid & 31, w = tid >> 5;

    if (tid < 256)
        s_ofs[tid] = g_hist[(seg * TILES + blockIdx.x) * 256 + tid];
    for (int q = tid; q < 8 * 256; q += 256)
        ((unsigned*)s_cnt)[q] = 0u;
    __syncthreads();

    unsigned long long r[16];
    unsigned short rk[16];
    unsigned char  dg[16];
    unsigned lml = (1u << lane) - 1u;

#pragma unroll
    for (int g = 0; g < 16; g++) {
        int p = w * 512 + g * 32 + lane;
        bool valid = p < n;
        unsigned d = 0x1FFu;
        if (valid) {
            r[g] = in[base + p];
            d = (unsigned)(r[g] >> shift) & 0xFFu;
            dg[g] = (unsigned char)d;
        }
        unsigned mask = __match_any_sync(0xFFFFFFFFu, d);
        int leader = __ffs(mask) - 1;
        unsigned prev = 0;
        if (lane == leader && valid)
            prev = atomicAdd(&s_cnt[w][d], __popc(mask));
        prev = __shfl_sync(0xFFFFFFFFu, prev, leader);
        if (valid) rk[g] = (unsigned short)(prev + __popc(mask & lml));
    }
    __syncthreads();

    if (tid < 256) {
        unsigned run = 0;
#pragma unroll
        for (int c = 0; c < 8; c++) {
            unsigned t = s_cnt[c][tid];
            s_cnt[c][tid] = run;
            run += t;
        }
    }
    __syncthreads();

#pragma unroll
    for (int g = 0; g < 16; g++) {
        int p = w * 512 + g * 32 + lane;
        if (p < n) {
            unsigned d = dg[g];
            out[s_ofs[d] + s_cnt[w][d] + rk[g]] = r[g];
        }
    }
}

// extract order + build vertex->position map (u16, valid when segLen<=65536)
__global__ void extractK(const int* __restrict__ rs, int V, int B) {
    int i = blockIdx.x * blockDim.x + threadIdx.x;
    if (i >= V) return;
    int v = (int)(g_recA[i] & 0xFFFFFFFFull);
    g_order[i] = v;
    int s = 0;
    while (s < B - 1 && i >= rs[s + 1]) s++;
    g_posMap[v] = (unsigned short)(i - rs[s]);
}

// ================= clustering FAST path: position-space resolution =========
// One block per segment (K==64, segLen<=65536). Helper warps pre-translate
// each candidate's neighbour row into order-positions (u16, smem) one
// super-window ahead, reading g_posMap from global (off critical path).
// Warp 0 resolves each 256-position window: 8-word alive mask in registers,
// __reduce_min_sync picks next center, out-of-window absorptions are
// fire-and-forget atomicOr into the position bitmap, rare in-window kills
// use an 8-word scratch merge. Invalid/self entries map to the row's own
// position (self-exclusion makes them no-ops). Backward absorptions are
// provably no-ops. ALL loops are hard-bounded (no spin can hang).
__global__ void __launch_bounds__(1024, 1)
clusterFastK(const int* __restrict__ neighs, const int* __restrict__ rs,
             int V, int K) {
    int seg = blockIdx.x;
    int s0 = rs[seg], s1 = rs[seg + 1];
    int segLen = s1 - s0;
    if (K != 64 || segLen > SEG_MAX) return;   // fallback kernel handles

    extern __shared__ int smemArr[];
    unsigned* assignedPos = (unsigned*)smemArr;                 // 2048 words
    unsigned* scratch     = (unsigned*)(smemArr + 2048);        // 8 words
    int*      vbuf        = smemArr + 2056;                     // 3*256 ints
    unsigned short* mrow  = (unsigned short*)(smemArr + 2824);  // 2*16384 u16

    int tid = threadIdx.x, lane = tid & 31, wid = tid >> 5;
    int nSW = (segLen + SW - 1) / SW;

    for (int q = tid; q < 2048; q += 1024) assignedPos[q] = 0u;
    if (tid < 8) scratch[tid] = 0u;
    __syncthreads();

    // ord for SW0, SW1
    for (int q = tid; q < 2 * SW; q += 1024) {
        int w = q >> 8, idx = q & 255;
        int p = w * SW + idx;
        if (w < nSW && p < segLen) vbuf[w * SW + idx] = g_order[s0 + p];
    }
    __syncthreads();

    // map SW0 (all 32 warps)
    if (nSW > 0) {
        int lim0 = min(SW, segLen);
        unsigned short* mr = mrow;            // slot 0
        for (int r = wid; r < lim0; r += 32) {
            int v = vbuf[r];
            unsigned short self16 = (unsigned short)r;
            int n0 = neighs[(size_t)v * 64 + lane];
            int n1 = neighs[(size_t)v * 64 + 32 + lane];
            int r0 = n0 - s0, r1 = n1 - s0;
            unsigned short j0 = (n0 >= 0 && (unsigned)r0 < (unsigned)segLen)
                              ? g_posMap[n0] : self16;
            unsigned short j1 = (n1 >= 0 && (unsigned)r1 < (unsigned)segLen)
                              ? g_posMap[n1] : self16;
            mr[r * 64 + lane] = j0;
            mr[r * 64 + 32 + lane] = j1;
        }
    }
    __syncthreads();

    // ---- main loop ----
    int cnt = 0;
    for (int s = 0; s < nSW; s++) {
        // helpers: map SW s+1, load ord for SW s+2
        int tgt = s + 1;
        if (wid != 0 && tgt < nSW) {
            int tBase = tgt * SW;
            int limT = min(SW, segLen - tBase);
            unsigned short* mr = mrow + (tgt & 1) * (SW * 64);
            const int* vb = vbuf + (tgt % 3) * SW;
            for (int r = wid - 1; r < limT; r += 31) {
                int v = vb[r];
                unsigned short self16 = (unsigned short)(tBase + r);
                int n0 = neighs[(size_t)v * 64 + lane];
                int n1 = neighs[(size_t)v * 64 + 32 + lane];
                int r0 = n0 - s0, r1 = n1 - s0;
                unsigned short j0 = (n0 >= 0 && (unsigned)r0 < (unsigned)segLen)
                                  ? g_posMap[n0] : self16;
                unsigned short j1 = (n1 >= 0 && (unsigned)r1 < (unsigned)segLen)
                                  ? g_posMap[n1] : self16;
                mr[r * 64 + lane] = j0;
                mr[r * 64 + 32 + lane] = j1;
            }
        }
        int t2 = s + 2;
        if (t2 < nSW && wid >= 1 && wid <= 8) {
            int idx = (wid - 1) * 32 + lane;
            int p = t2 * SW + idx;
            if (p < segLen) vbuf[(t2 % 3) * SW + idx] = g_order[s0 + p];
        }

        // warp 0: resolve super-window s
        if (wid == 0) {
            int swBase = s * SW;
            const unsigned short* mr = mrow + (s & 1) * (SW * 64);
            const int* vb = vbuf + (s % 3) * SW;

            unsigned aw = 0u;
            if (lane < 8) {
                int base = swBase + lane * 32;
                int nb = segLen - base;
                unsigned valid = (nb >= 32) ? ~0u
                               : (nb <= 0 ? 0u : ((1u << nb) - 1u));
                aw = ~assignedPos[(swBase >> 5) + lane] & valid;
            }

            // each iteration clears >=1 of 256 alive bits -> bound SW is exact
            for (int guard = 0; guard < SW; guard++) {
                unsigned cand = 1024u;
                if (lane < 8 && aw) cand = lane * 32 + (__ffs(aw) - 1);
                unsigned l = __reduce_min_sync(0xFFFFFFFFu, cand);
                if (l >= (unsigned)SW) break;

                unsigned j0 = mr[l * 64 + lane];
                unsigned j1 = mr[l * 64 + 32 + lane];
                unsigned rel0 = j0 - (unsigned)swBase;   // wraps for past positions
                unsigned rel1 = j1 - (unsigned)swBase;
                bool in0 = rel0 < (unsigned)SW;
                bool in1 = rel1 < (unsigned)SW;
                bool h0 = in0 && (rel0 != l);
                bool h1 = in1 && (rel1 != l);
                if (!in0) atomicOr(&assignedPos[j0 >> 5], 1u << (j0 & 31));
                if (!in1) atomicOr(&assignedPos[j1 >> 5], 1u << (j1 & 31));

                unsigned bal = __ballot_sync(0xFFFFFFFFu, h0 | h1);
                if (bal) {                       // rare in-window kills
                    if (h0) atomicOr(&scratch[rel0 >> 5], 1u << (rel0 & 31));
                    if (h1) atomicOr(&scratch[rel1 >> 5], 1u << (rel1 & 31));
                    __syncwarp();
                    if (lane < 8) { aw &= ~scratch[lane]; scratch[lane] = 0u; }
                    __syncwarp();
                }
                if (lane == (int)(l >> 5)) aw &= ~(1u << (l & 31));
                if (lane == 0) g_selLocal[s0 + cnt] = vb[l];
                cnt++;
            }
        }
        __syncthreads();
    }
    if (wid == 0 && lane == 0) g_segCount[seg] = cnt;
}

// ================= clustering fallback (round-12 proven kernel) ===========
__global__ void __launch_bounds__(1024, 1)
clusterOldK(const int* __restrict__ neighs, const int* __restrict__ rs,
            int V, int K) {
    int seg = blockIdx.x;
    int s0 = rs[seg], s1 = rs[seg + 1];
    if (K == 64 && (s1 - s0) <= SEG_MAX) return;   // fast path handled it

    extern __shared__ int smemArr[];
    int segLen = s1 - s0;
    int bw = (segLen + 31) >> 5;
    unsigned int* bitmap = (unsigned int*)smemArr;
    int tid = threadIdx.x, lane = tid & 31, wid = tid >> 5;

    for (int w = tid; w < bw; w += blockDim.x) bitmap[w] = 0u;
    __syncthreads();

    if (wid == 0) {
        int cnt = 0;
        for (int i = s0; i < s1; i += 32) {
            int m = min(32, s1 - i);
            int v = (lane < m) ? g_order[i + lane] : 0;
            bool a = false;
            if (lane < m) {
                int rel = v - s0;
                a = !((bitmap[rel >> 5] >> (rel & 31)) & 1u);
            }
            unsigned alive = __ballot_sync(0xFFFFFFFFu, a);
            while (alive) {
                int l = __ffs(alive) - 1;
                int cv = __shfl_sync(0xFFFFFFFFu, v, l);
                if (lane == 0) g_selLocal[s0 + cnt] = cv;
                const int* row = neighs + (size_t)cv * K;
                for (int t = lane; t < K; t += 32) {
                    int n = row[t];
                    int rel = n - s0;
                    if (n >= 0 && (unsigned)rel < (unsigned)segLen)
                        atomicOr(&bitmap[rel >> 5], 1u << (rel & 31));
                }
                cnt++;
                __syncwarp();
                bool a2 = false;
                if (lane < m && lane > l) {
                    int rel = v - s0;
                    a2 = !((bitmap[rel >> 5] >> (rel & 31)) & 1u);
                }
                alive = __ballot_sync(0xFFFFFFFFu, a2);
            }
        }
        if (lane == 0) g_segCount[seg] = cnt;
    }
}

// ---------------- phase 2: gg via parallel atomicMin ----------------
__global__ void minK(const int* __restrict__ neighs, const int* __restrict__ rs,
                     int V, int K, int B) {
    int idx = blockIdx.x * blockDim.x + threadIdx.x;
    int p = idx >> 2, q = idx & 3;
    if (p >= V) return;
    int s = 0;
    while (s < B - 1 && p >= rs[s + 1]) s++;
    int s0 = rs[s];
    int local = p - s0;
    if (local >= g_segCount[s]) return;
    int segLen = rs[s + 1] - s0;
    int cv = g_selLocal[p];
    if (q == 0) atomicMin(&g_ggLocal[cv], local);
    int per = (K + 3) >> 2;
    int t0 = q * per, t1 = min(K, t0 + per);
    const int* row = neighs + (size_t)cv * K;
    for (int t = t0; t < t1; t++) {
        int n = row[t];
        int rel = n - s0;
        if (n >= 0 && (unsigned)rel < (unsigned)segLen)
            atomicMin(&g_ggLocal[n], local);
    }
}

// ---------------- finalize (float32 outputs) ----------------
__global__ void finalizeK(float* __restrict__ rsn, int B) {
    int a = 0;
    rsn[0] = 0.0f; g_rsn[0] = 0;
    for (int s = 0; s < B; s++) {
        a += g_segCount[s];
        rsn[s + 1] = (float)a;
        g_rsn[s + 1] = a;
    }
}

__global__ void fixK(const int* __restrict__ rs, float* __restrict__ sel,
                     float* __restrict__ gg, int V, int B) {
    int i = blockIdx.x * blockDim.x + threadIdx.x;
    if (i >= V) return;
    int s = 0;
    while (s < B - 1 && i >= rs[s + 1]) s++;
    gg[i] = (float)(g_ggLocal[i] + g_rsn[s]);
    int t = i - rs[s];
    if (t < g_segCount[s]) sel[g_rsn[s] + t] = (float)g_selLocal[i];
    if (i >= g_rsn[B]) sel[i] = -1.0f;
}

// ---------------- launch ----------------
extern "C" void kernel_launch(void* const* d_in, const int* in_sizes, int n_in,
                              void* d_out, int out_size) {
    long s[3] = { in_sizes[0], in_sizes[1], in_sizes[2] };
    int big = 0, small = 0;
    for (int i = 1; i < 3; i++) {
        if (s[i] > s[big]) big = i;
        if (s[i] < s[small]) small = i;
    }
    int mid = 3 - big - small;
    const int*   neighs = (const int*)d_in[big];
    const float* hier   = (const float*)d_in[mid];
    const int*   rs     = (const int*)d_in[small];

    int V = in_sizes[mid];
    int K = in_sizes[big] / V;
    int B = in_sizes[small] - 1;
    if (V > V_MAX || B > B_MAX || B < 1) return;

    float* out = (float*)d_out;
    float* sel = out;
    float* rsn = out + V;
    float* gg  = out + V + B + 1;

    int TILES = (V + TILE - 1) / TILE;
    if (TILES > TILES_MAX) return;

    int nb = (V + 255) / 256;
    packK<<<nb, 256>>>(hier, V);

    for (int p = 0; p < 4; p++) {
        int dir = p & 1;
        int shift = 32 + 8 * p;
        dim3 grid(TILES, B);
        histK<<<grid, 256>>>(dir, shift, TILES, rs);
        scanK<<<B, 256>>>(TILES, rs);
        scatterK<<<grid, 256>>>(dir, shift, TILES, rs);
    }
    extractK<<<nb, 256>>>(rs, V, B);

    // fast-path smem: assignedPos(2048) + scratch(8) + vbuf(768) +
    //                 mrow(16384 int-words)  = 19208 ints = 76,832 B
    size_t smemFast = (size_t)(2048 + 8 + 768 + 16384) * 4;
    size_t smemOld  = (size_t)((V + 31) >> 5) * 4 + 1024;

    cudaStreamCaptureStatus cs = cudaStreamCaptureStatusNone;
    cudaStreamIsCapturing((cudaStream_t)0, &cs);
    if (cs == cudaStreamCaptureStatusNone) {
        cudaFuncSetAttribute(clusterFastK,
                             cudaFuncAttributeMaxDynamicSharedMemorySize,
                             (int)smemFast);
        cudaFuncSetAttribute(clusterOldK,
                             cudaFuncAttributeMaxDynamicSharedMemorySize,
                             (int)smemOld);
    }

    clusterFastK<<<B, 1024, smemFast>>>(neighs, rs, V, K);
    clusterOldK<<<B, 1024, smemOld>>>(neighs, rs, V, K);

    minK<<<(V * 4 + 255) / 256, 256>>>(neighs, rs, V, K, B);
    finalizeK<<<1, 1>>>(rsn, B);
    fixK<<<nb, 256>>>(rs, sel, gg, V, B);
}